// round 10
// baseline (speedup 1.0000x reference)
#include <cuda_runtime.h>
#include <stdint.h>

// MXFP (E2M1-like, group=32) quantize-dequantize, bit-exact vs the JAX reference.
// Round 10: best-of-session composite. R6's 256-bit load path (4 slabs of
// ld.global.cs.v8.b32, 8 floats/thread/slab, 2-shuffle width-4 butterfly,
// half the threads/instructions of the float4 variants) + R9's Veltkamp FMA
// rounding (RNE to 2 sig bits in 3 FMA-pipe ops) + plain streaming .cs
// float4 stores (R5/R6 showed evict_last stores poison the next graph
// replay's read stream; .cs is the clean steady-state policy).

__device__ __forceinline__ float mxfp_q1(float x, float inv_scale, float scale) {
    float xd = x * inv_scale;                        // exact (power-of-two scale)
    // Veltkamp split: RNE to 2 significant bits. |xd| < 8 so no overflow.
    float c = fmaf(xd, 4194304.0f, xd);              // xd*(2^22+1), single rounding
    float h = c - (c - xd);                          // RNE(xd -> 2 sig bits)
    float a = fminf(fmaxf(fabsf(h), 0.5f), 6.0f);    // clamp [min_repr, max_repr]
    if (fabsf(xd) <= 0.25f) a = 0.0f;                // lim_zero flush (covers 0/denorm)
    float y = copysignf(a, xd);
    return y * scale;                                // exact (power-of-two scale)
}

// 256-bit load, evict-first (streaming read-once data).
__device__ __forceinline__ void ld_cs_v8(const float* p, float* v) {
    uint32_t r0, r1, r2, r3, r4, r5, r6, r7;
    asm volatile("ld.global.cs.v8.b32 {%0,%1,%2,%3,%4,%5,%6,%7}, [%8];"
                 : "=r"(r0), "=r"(r1), "=r"(r2), "=r"(r3),
                   "=r"(r4), "=r"(r5), "=r"(r6), "=r"(r7)
                 : "l"(p));
    v[0] = __uint_as_float(r0); v[1] = __uint_as_float(r1);
    v[2] = __uint_as_float(r2); v[3] = __uint_as_float(r3);
    v[4] = __uint_as_float(r4); v[5] = __uint_as_float(r5);
    v[6] = __uint_as_float(r6); v[7] = __uint_as_float(r7);
}

__global__ __launch_bounds__(256) void mxfp_kernel(const float* __restrict__ in,
                                                   float* __restrict__ out,
                                                   int slabF, int nthreads) {
    int i = blockIdx.x * blockDim.x + threadIdx.x;
    if (i >= nthreads) return;

    long base = (long)i * 8;

    // ---- front-batched: 4 independent 256-bit streaming loads ----
    float v[4][8];
#pragma unroll
    for (int k = 0; k < 4; k++)
        ld_cs_v8(in + base + (long)k * slabF, v[k]);

    // ---- local max|.| over this thread's 8 floats per chunk ----
    float m[4];
#pragma unroll
    for (int k = 0; k < 4; k++) {
        float a = fmaxf(fmaxf(fabsf(v[k][0]), fabsf(v[k][1])),
                        fmaxf(fabsf(v[k][2]), fabsf(v[k][3])));
        float b = fmaxf(fmaxf(fabsf(v[k][4]), fabsf(v[k][5])),
                        fmaxf(fabsf(v[k][6]), fabsf(v[k][7])));
        m[k] = fmaxf(a, b);
    }

    // ---- 4 independent width-4 butterfly reductions (2 stages, interleaved) ----
#pragma unroll
    for (int k = 0; k < 4; k++) m[k] = fmaxf(m[k], __shfl_xor_sync(0xFFFFFFFFu, m[k], 1));
#pragma unroll
    for (int k = 0; k < 4; k++) m[k] = fmaxf(m[k], __shfl_xor_sync(0xFFFFFFFFu, m[k], 2));

#pragma unroll
    for (int k = 0; k < 4; k++) {
        float mk = (m[k] == 0.0f) ? 1.0f : m[k];
        int e   = (int)(__float_as_uint(mk) >> 23) - 127;  // floor(log2) for normal mk
        int pot = e - 2;
        if (pot < -127) pot = -127;

        float inv_scale = __uint_as_float((uint32_t)(127 - pot) << 23);   // 2^-pot
        float scale = (pot >= -126)
                    ? __uint_as_float((uint32_t)(pot + 127) << 23)        // normal 2^pot
                    : __uint_as_float(0x00400000u);                       // denormal 2^-127

        float4 o0, o1;
        o0.x = mxfp_q1(v[k][0], inv_scale, scale);
        o0.y = mxfp_q1(v[k][1], inv_scale, scale);
        o0.z = mxfp_q1(v[k][2], inv_scale, scale);
        o0.w = mxfp_q1(v[k][3], inv_scale, scale);
        o1.x = mxfp_q1(v[k][4], inv_scale, scale);
        o1.y = mxfp_q1(v[k][5], inv_scale, scale);
        o1.z = mxfp_q1(v[k][6], inv_scale, scale);
        o1.w = mxfp_q1(v[k][7], inv_scale, scale);

        float4* op = (float4*)(out + base + (long)k * slabF);
        __stcs(op + 0, o0);   // streaming store, evict-first
        __stcs(op + 1, o1);
    }
}

extern "C" void kernel_launch(void* const* d_in, const int* in_sizes, int n_in,
                              void* d_out, int out_size) {
    const float* x = (const float*)d_in[0];
    float* y = (float*)d_out;
    int n = in_sizes[0];               // 33,554,432 floats
    int slabF = n / 4;                 // 8,388,608 floats per slab
    int nthreads = slabF / 8;          // 1,048,576 threads
    int threads = 256;
    int blocks = (nthreads + threads - 1) / threads;   // 4096
    mxfp_kernel<<<blocks, threads>>>(x, y, slabF, nthreads);
}

// round 11
// speedup vs baseline: 1.0384x; 1.0384x over previous
#include <cuda_runtime.h>
#include <stdint.h>

// MXFP (E2M1-like, group=32) quantize-dequantize, bit-exact vs the JAX reference.
// Round 11: R2 body (the session best: 4 coalesced float4 slabs, MLP=4
// front-batched LDG.128, width-8 3-stage butterfly, magic-add RNE, .cs
// streaming loads+stores) with 128-thread blocks (16384 CTAs) for finer
// work-stealing granularity and smaller tail-wave imbalance. Per-warp
// instruction stream and coalescing identical to R2.
//
// Session findings (all falsified levers): MLP 4->8, v8 256-bit path, L2
// evict_last on stores AND on loads, persistent single-wave grid, ALU-pipe
// halving -- every config pins at 268MB / ~6.16 TB/s steady-state mixed
// r/w HBM ceiling. This kernel sits on that roofline.

__device__ __forceinline__ float mxfp_q1(float x, float inv_scale, float scale) {
    float xd = x * inv_scale;                       // exact (power-of-two scale)
    uint32_t bb = __float_as_uint(xd);
    uint32_t eb = bb & 0x7F800000u;                 // exponent field
    // mans*2 = |xd| * 2^(1-e);  m2 in [2,4) for normal xd
    float m2 = fabsf(xd) * __uint_as_float(0x7F800000u - eb);
    // RNE to integer via magic constant (matches rintf/jnp.round here)
    float r = (m2 + 12582912.0f) - 12582912.0f;
    // x_rnd = r * 2^(e-1)
    float ra = r * __uint_as_float(eb - 0x00800000u);
    ra = fminf(fmaxf(ra, 0.5f), 6.0f);              // clamp [min_repr, max_repr]
    if (fabsf(xd) <= 0.25f) ra = 0.0f;              // lim_zero flush (handles 0/denorm paths)
    uint32_t rb = (__float_as_uint(ra) & 0x7FFFFFFFu) | (bb & 0x80000000u);
    return __uint_as_float(rb) * scale;             // exact (power-of-two scale)
}

__device__ __forceinline__ float maxabs4(float4 v) {
    return fmaxf(fmaxf(fabsf(v.x), fabsf(v.y)), fmaxf(fabsf(v.z), fabsf(v.w)));
}

__device__ __forceinline__ float4 q4(float4 v, float inv_scale, float scale) {
    float4 o;
    o.x = mxfp_q1(v.x, inv_scale, scale);
    o.y = mxfp_q1(v.y, inv_scale, scale);
    o.z = mxfp_q1(v.z, inv_scale, scale);
    o.w = mxfp_q1(v.w, inv_scale, scale);
    return o;
}

__global__ __launch_bounds__(128) void mxfp_kernel(const float4* __restrict__ in,
                                                   float4* __restrict__ out,
                                                   int nq) {
    int i = blockIdx.x * blockDim.x + threadIdx.x;
    if (i >= nq) return;

    // ---- front-batched: 4 independent, fully-coalesced LDG.128 ----
    float4 v[4];
#pragma unroll
    for (int k = 0; k < 4; k++)
        v[k] = __ldcs(in + i + k * nq);

    // ---- local max|.| per chunk ----
    float m[4];
#pragma unroll
    for (int k = 0; k < 4; k++)
        m[k] = maxabs4(v[k]);

    // ---- 4 independent width-8 butterfly reductions, stages interleaved ----
#pragma unroll
    for (int k = 0; k < 4; k++) m[k] = fmaxf(m[k], __shfl_xor_sync(0xFFFFFFFFu, m[k], 1));
#pragma unroll
    for (int k = 0; k < 4; k++) m[k] = fmaxf(m[k], __shfl_xor_sync(0xFFFFFFFFu, m[k], 2));
#pragma unroll
    for (int k = 0; k < 4; k++) m[k] = fmaxf(m[k], __shfl_xor_sync(0xFFFFFFFFu, m[k], 4));

#pragma unroll
    for (int k = 0; k < 4; k++) {
        float mk = (m[k] == 0.0f) ? 1.0f : m[k];
        int e   = (int)(__float_as_uint(mk) >> 23) - 127;  // floor(log2) for normal mk
        int pot = e - 2;
        if (pot < -127) pot = -127;

        float inv_scale = __uint_as_float((uint32_t)(127 - pot) << 23);   // 2^-pot
        float scale = (pot >= -126)
                    ? __uint_as_float((uint32_t)(pot + 127) << 23)        // normal 2^pot
                    : __uint_as_float(0x00400000u);                       // denormal 2^-127

        __stcs(out + i + k * nq, q4(v[k], inv_scale, scale));
    }
}

extern "C" void kernel_launch(void* const* d_in, const int* in_sizes, int n_in,
                              void* d_out, int out_size) {
    const float4* x = (const float4*)d_in[0];
    float4* y = (float4*)d_out;
    int n4 = in_sizes[0] / 4;          // 8,388,608 float4
    int nq = n4 / 4;                   // 2,097,152 float4 per slab
    int threads = 128;
    int blocks = (nq + threads - 1) / threads;   // 16384
    mxfp_kernel<<<blocks, threads>>>(x, y, nq);
}

// round 12
// speedup vs baseline: 1.0392x; 1.0007x over previous
#include <cuda_runtime.h>
#include <stdint.h>

// MXFP (E2M1-like, group=32) quantize-dequantize, bit-exact vs the JAX reference.
// FINAL (R2 body, session best 43.49us): 4 coalesced float4 slabs per thread
// (MLP=4 front-batched LDG.128), 8 lanes per group with a 3-stage width-8
// butterfly max-reduction, all log2/exp2 via exponent-field bit tricks
// (zero MUFU), magic-constant RNE rounding, streaming .cs loads and stores.
//
// Roofline: 134MB read + 134MB write per iteration is mandatory; every
// measured configuration (11 rounds: MLP/occupancy/vector-width/L2-residency/
// persistence/ALU-reduction sweeps) pins at ~6.16 TB/s steady-state mixed
// r/w HBM throughput => ~43.5us is the hardware floor. This kernel sits on it
// with rel_err = 0.0 (bit-exact vs the JAX reference).

__device__ __forceinline__ float mxfp_q1(float x, float inv_scale, float scale) {
    float xd = x * inv_scale;                       // exact (power-of-two scale)
    uint32_t bb = __float_as_uint(xd);
    uint32_t eb = bb & 0x7F800000u;                 // exponent field
    // mans*2 = |xd| * 2^(1-e);  m2 in [2,4) for normal xd
    float m2 = fabsf(xd) * __uint_as_float(0x7F800000u - eb);
    // RNE to integer via magic constant (matches rintf / jnp.round here)
    float r = (m2 + 12582912.0f) - 12582912.0f;
    // x_rnd = r * 2^(e-1)
    float ra = r * __uint_as_float(eb - 0x00800000u);
    ra = fminf(fmaxf(ra, 0.5f), 6.0f);              // clamp [min_repr, max_repr]
    if (fabsf(xd) <= 0.25f) ra = 0.0f;              // lim_zero flush (handles 0/denorm paths)
    uint32_t rb = (__float_as_uint(ra) & 0x7FFFFFFFu) | (bb & 0x80000000u);
    return __uint_as_float(rb) * scale;             // exact (power-of-two scale)
}

__device__ __forceinline__ float maxabs4(float4 v) {
    return fmaxf(fmaxf(fabsf(v.x), fabsf(v.y)), fmaxf(fabsf(v.z), fabsf(v.w)));
}

__device__ __forceinline__ float4 q4(float4 v, float inv_scale, float scale) {
    float4 o;
    o.x = mxfp_q1(v.x, inv_scale, scale);
    o.y = mxfp_q1(v.y, inv_scale, scale);
    o.z = mxfp_q1(v.z, inv_scale, scale);
    o.w = mxfp_q1(v.w, inv_scale, scale);
    return o;
}

__global__ __launch_bounds__(256) void mxfp_kernel(const float4* __restrict__ in,
                                                   float4* __restrict__ out,
                                                   int nq) {
    int i = blockIdx.x * blockDim.x + threadIdx.x;
    if (i >= nq) return;

    // ---- front-batched: 4 independent, fully-coalesced LDG.128 ----
    float4 v[4];
#pragma unroll
    for (int k = 0; k < 4; k++)
        v[k] = __ldcs(in + i + k * nq);

    // ---- local max|.| per chunk ----
    float m[4];
#pragma unroll
    for (int k = 0; k < 4; k++)
        m[k] = maxabs4(v[k]);

    // ---- 4 independent width-8 butterfly reductions, stages interleaved ----
#pragma unroll
    for (int k = 0; k < 4; k++) m[k] = fmaxf(m[k], __shfl_xor_sync(0xFFFFFFFFu, m[k], 1));
#pragma unroll
    for (int k = 0; k < 4; k++) m[k] = fmaxf(m[k], __shfl_xor_sync(0xFFFFFFFFu, m[k], 2));
#pragma unroll
    for (int k = 0; k < 4; k++) m[k] = fmaxf(m[k], __shfl_xor_sync(0xFFFFFFFFu, m[k], 4));

#pragma unroll
    for (int k = 0; k < 4; k++) {
        float mk = (m[k] == 0.0f) ? 1.0f : m[k];
        int e   = (int)(__float_as_uint(mk) >> 23) - 127;  // floor(log2) for normal mk
        int pot = e - 2;
        if (pot < -127) pot = -127;

        float inv_scale = __uint_as_float((uint32_t)(127 - pot) << 23);   // 2^-pot
        float scale = (pot >= -126)
                    ? __uint_as_float((uint32_t)(pot + 127) << 23)        // normal 2^pot
                    : __uint_as_float(0x00400000u);                       // denormal 2^-127

        __stcs(out + i + k * nq, q4(v[k], inv_scale, scale));
    }
}

extern "C" void kernel_launch(void* const* d_in, const int* in_sizes, int n_in,
                              void* d_out, int out_size) {
    const float4* x = (const float4*)d_in[0];
    float4* y = (float4*)d_out;
    int n4 = in_sizes[0] / 4;          // 8,388,608 float4
    int nq = n4 / 4;                   // 2,097,152 float4 per slab
    int threads = 256;
    int blocks = (nq + threads - 1) / threads;   // 8192
    mxfp_kernel<<<blocks, threads>>>(x, y, nq);
}